// round 14
// baseline (speedup 1.0000x reference)
#include <cuda_runtime.h>
#include <cuda_bf16.h>
#include <cstdint>

// CustomEmbedding via TMA bulk copies:
//   regular token (id>=1000): cp.async.bulk G2S (weight row -> SMEM slot),
//                             then cp.async.bulk S2G (SMEM slot -> out row).
//                             Rows never touch registers/LSU.
//   numeric token (id<1000):  sin((id/1000)*(i+1)) computed by threads,
//                             stored directly to out (overlaps the TMA fetch).
// 128-thread block handles 16 tokens (16 x 2KB SMEM slots). Grid = 2048.

#define TOK_PER_BLK 16
#define ROW_BYTES   2048     // 512 floats
#define BLK_THREADS 128

static __device__ __forceinline__ uint32_t smem_u32(const void* p) {
    return (uint32_t)__cvta_generic_to_shared(p);
}

__global__ void __launch_bounds__(BLK_THREADS)
embed_kernel(const int* __restrict__ x,
             const float* __restrict__ w,    // [VOCAB, 512]
             float* __restrict__ out,        // [N, 512]
             int n_tokens)
{
    __shared__ alignas(128) uint8_t s_rows[TOK_PER_BLK][ROW_BYTES];
    __shared__ uint64_t s_mbar;
    __shared__ int s_ids[TOK_PER_BLK];

    const int tid = threadIdx.x;
    const int t0  = blockIdx.x * TOK_PER_BLK;

    if (tid < TOK_PER_BLK) s_ids[tid] = __ldg(x + t0 + tid);
    if (tid == 0) {
        asm volatile("mbarrier.init.shared.b64 [%0], 1;"
                     :: "r"(smem_u32(&s_mbar)) : "memory");
    }
    __syncthreads();

    const uint32_t mb = smem_u32(&s_mbar);

    // ---- elected thread: expect_tx + issue G2S bulk copies for regular ids
    if (tid == 0) {
        int total = 0;
        #pragma unroll
        for (int q = 0; q < TOK_PER_BLK; q++)
            if (s_ids[q] >= 1000) total += ROW_BYTES;

        asm volatile("mbarrier.arrive.expect_tx.shared.b64 _, [%0], %1;"
                     :: "r"(mb), "r"(total) : "memory");

        const int sz = ROW_BYTES;
        #pragma unroll
        for (int q = 0; q < TOK_PER_BLK; q++) {
            int id = s_ids[q];
            if (id >= 1000) {
                const void* src = w + (size_t)id * 512;
                uint32_t    dst = smem_u32(&s_rows[q][0]);
                asm volatile(
                    "cp.async.bulk.shared::cluster.global"
                    ".mbarrier::complete_tx::bytes [%0], [%1], %2, [%3];"
                    :: "r"(dst), "l"(src), "r"(sz), "r"(mb) : "memory");
            }
        }
    }

    // ---- numeric tokens (~2%): compute directly to out, overlapping TMA
    for (int q = 0; q < TOK_PER_BLK; q++) {
        int id = s_ids[q];
        if (id < 1000) {
            float s  = (float)id * 1e-3f;
            float* o = out + (size_t)(t0 + q) * 512;
            int i = tid * 4;                    // 4 floats per thread, 128 thr
            float4 v;
            v.x = sinf(s * (float)(i + 1));
            v.y = sinf(s * (float)(i + 2));
            v.z = sinf(s * (float)(i + 3));
            v.w = sinf(s * (float)(i + 4));
            __stcs((float4*)(o + i), v);
        }
    }

    // ---- wait for all G2S transfers
    asm volatile(
        "{\n\t"
        ".reg .pred P;\n\t"
        "WAIT_%=:\n\t"
        "mbarrier.try_wait.parity.shared.b64 P, [%0], %1;\n\t"
        "@!P bra WAIT_%=;\n\t"
        "}"
        :: "r"(mb), "r"(0u) : "memory");

    // ---- elected thread: S2G bulk copies SMEM slot -> out row
    if (tid == 0) {
        const int sz = ROW_BYTES;
        #pragma unroll
        for (int q = 0; q < TOK_PER_BLK; q++) {
            int id = s_ids[q];
            if (id >= 1000) {
                void*    dstg = out + (size_t)(t0 + q) * 512;
                uint32_t srcs = smem_u32(&s_rows[q][0]);
                asm volatile(
                    "cp.async.bulk.global.shared::cta.bulk_group [%0], [%1], %2;"
                    :: "l"(dstg), "r"(srcs), "r"(sz) : "memory");
            }
        }
        asm volatile("cp.async.bulk.commit_group;" ::: "memory");
        asm volatile("cp.async.bulk.wait_group.read 0;" ::: "memory");
    }
    // keep CTA (and its SMEM) alive until the S2G reads are done
    __syncthreads();
}

extern "C" void kernel_launch(void* const* d_in, const int* in_sizes, int n_in,
                              void* d_out, int out_size)
{
    // metadata order: x (int32), weight (float32), num_value (int32), is_num (bool)
    const int*   x = (const int*)d_in[0];
    const float* w = (const float*)d_in[1];
    float*     out = (float*)d_out;

    int n_tokens = in_sizes[0];                       // 32768
    int blocks   = (n_tokens + TOK_PER_BLK - 1) / TOK_PER_BLK;  // 2048

    embed_kernel<<<blocks, BLK_THREADS>>>(x, w, out, n_tokens);
}

// round 15
// speedup vs baseline: 1.0305x; 1.0305x over previous
#include <cuda_runtime.h>
#include <cuda_bf16.h>

// CustomEmbedding: out[t, :] = sin((id/1000)*(i+1)) if id<1000 else weight[id, :]
// Tokens: 8*4096 = 32768, DIM = 512 floats = 128 float4 per row.
// One WARP per TWO tokens (best measured shape, R6 = 16.10us with __stcs):
//   - both ids fetched with a single int2 LDG (broadcast)
//   - 8 independent row LDG.128s front-batched (per-thread MLP = 8)
//   - output stores PLAIN WRITE-BACK: dirty output lines stay resident in L2
//     across graph replays (touched weights ~50MB + output 64MB < 126MB L2),
//     taking the DRAM write drain off the critical path.
// 256-thread block = 8 warps = 16 tokens; grid = 2048 blocks.

#define DIM4 128            // 512 floats / 4

__device__ __forceinline__ float4 sin4(float s, int jj) {
    float b = (float)(jj * 4);
    float4 v;
    v.x = sinf(s * (b + 1.0f));
    v.y = sinf(s * (b + 2.0f));
    v.z = sinf(s * (b + 3.0f));
    v.w = sinf(s * (b + 4.0f));
    return v;
}

__global__ void __launch_bounds__(256)
embed_kernel(const int2* __restrict__ x2,    // token ids, viewed as pairs
             const float4* __restrict__ w,   // [VOCAB, DIM4]
             float4* __restrict__ out,       // [N, DIM4]
             int n_pairs)
{
    int warp = (blockIdx.x * blockDim.x + threadIdx.x) >> 5;  // global warp = pair idx
    int j    = threadIdx.x & 31;                              // lane -> float4 idx base
    if (warp >= n_pairs) return;

    int2 ids = __ldg(x2 + warp);        // one 8B load, broadcast across warp
    int  id0 = ids.x, id1 = ids.y;
    int  t0  = warp * 2;

    const float4* r0 = w + (size_t)id0 * DIM4;
    const float4* r1 = w + (size_t)id1 * DIM4;

    float4 a0, a1, a2, a3, b0, b1, b2, b3;

    if (id0 >= 1000 && id1 >= 1000) {
        // fast path (~96% of warps): 8 independent loads, front-batched
        a0 = __ldg(r0 + j);
        a1 = __ldg(r0 + j + 32);
        a2 = __ldg(r0 + j + 64);
        a3 = __ldg(r0 + j + 96);
        b0 = __ldg(r1 + j);
        b1 = __ldg(r1 + j + 32);
        b2 = __ldg(r1 + j + 64);
        b3 = __ldg(r1 + j + 96);
    } else {
        if (id0 < 1000) {
            float s = (float)id0 * 1e-3f;
            a0 = sin4(s, j); a1 = sin4(s, j + 32);
            a2 = sin4(s, j + 64); a3 = sin4(s, j + 96);
        } else {
            a0 = __ldg(r0 + j);      a1 = __ldg(r0 + j + 32);
            a2 = __ldg(r0 + j + 64); a3 = __ldg(r0 + j + 96);
        }
        if (id1 < 1000) {
            float s = (float)id1 * 1e-3f;
            b0 = sin4(s, j); b1 = sin4(s, j + 32);
            b2 = sin4(s, j + 64); b3 = sin4(s, j + 96);
        } else {
            b0 = __ldg(r1 + j);      b1 = __ldg(r1 + j + 32);
            b2 = __ldg(r1 + j + 64); b3 = __ldg(r1 + j + 96);
        }
    }

    float4* o0 = out + (size_t)t0 * DIM4;
    float4* o1 = o0 + DIM4;
    o0[j]      = a0;
    o0[j + 32] = a1;
    o0[j + 64] = a2;
    o0[j + 96] = a3;
    o1[j]      = b0;
    o1[j + 32] = b1;
    o1[j + 64] = b2;
    o1[j + 96] = b3;
}

extern "C" void kernel_launch(void* const* d_in, const int* in_sizes, int n_in,
                              void* d_out, int out_size)
{
    // metadata order: x (int32), weight (float32), num_value (int32), is_num (bool)
    const int2*   x2 = (const int2*)d_in[0];
    const float4* w  = (const float4*)d_in[1];
    float4*      out = (float4*)d_out;

    int n_tokens = in_sizes[0];           // 32768 (even)
    int n_pairs  = n_tokens / 2;          // 16384 warps
    int blocks   = (n_pairs * 32 + 255) / 256;   // 2048

    embed_kernel<<<blocks, 256>>>(x2, w, out, n_pairs);
}

// round 16
// speedup vs baseline: 1.1402x; 1.1064x over previous
#include <cuda_runtime.h>
#include <cuda_bf16.h>

// CustomEmbedding: out[t, :] = sin((id/1000)*(i+1)) if id<1000 else weight[id, :]
// Tokens: 8*4096 = 32768, DIM = 512 floats = 64 x 32B chunks per row.
// One WARP per TWO tokens (best measured shape R6 = 16.10us), upgraded to
// 256-bit vector memory ops (sm_100+ ld/st.global.v8.f32):
//   - both ids fetched with a single int2 LDG (broadcast)
//   - 4 independent LDG.256 (.nc) per thread, front-batched
//   - 4 STG.256 with evict-first (.cs) policy — proven best store policy
// Halves LDG/STG instruction count vs 128-bit version at identical traffic.
// 256-thread block = 8 warps = 16 tokens; grid = 2048 blocks.

#define DIM 512

__device__ __forceinline__ void ldg256(const float* p, float* v) {
    asm volatile("ld.global.nc.v8.f32 {%0,%1,%2,%3,%4,%5,%6,%7}, [%8];"
                 : "=f"(v[0]), "=f"(v[1]), "=f"(v[2]), "=f"(v[3]),
                   "=f"(v[4]), "=f"(v[5]), "=f"(v[6]), "=f"(v[7])
                 : "l"(p));
}

__device__ __forceinline__ void stg256_cs(float* p, const float* v) {
    asm volatile("st.global.cs.v8.f32 [%0], {%1,%2,%3,%4,%5,%6,%7,%8};"
                 :: "l"(p),
                    "f"(v[0]), "f"(v[1]), "f"(v[2]), "f"(v[3]),
                    "f"(v[4]), "f"(v[5]), "f"(v[6]), "f"(v[7])
                 : "memory");
}

__device__ __forceinline__ void sin8(float s, int base, float* v) {
    #pragma unroll
    for (int k = 0; k < 8; k++)
        v[k] = sinf(s * (float)(base + k + 1));
}

__global__ void __launch_bounds__(256)
embed_kernel(const int2* __restrict__ x2,    // token ids, viewed as pairs
             const float* __restrict__ w,    // [VOCAB, DIM]
             float* __restrict__ out,        // [N, DIM]
             int n_pairs)
{
    int warp = (blockIdx.x * blockDim.x + threadIdx.x) >> 5;  // global warp = pair idx
    int j    = threadIdx.x & 31;                              // lane
    if (warp >= n_pairs) return;

    int2 ids = __ldg(x2 + warp);        // one 8B load, broadcast across warp
    int  id0 = ids.x, id1 = ids.y;
    int  t0  = warp * 2;

    // chunk indices: lane j handles 32B-chunks j and j+32 of each row
    const int c0 = j * 8;               // float offset of chunk j
    const int c1 = (j + 32) * 8;        // float offset of chunk j+32

    const float* r0 = w + (size_t)id0 * DIM;
    const float* r1 = w + (size_t)id1 * DIM;

    float a0[8], a1[8], b0[8], b1[8];

    if (id0 >= 1000 && id1 >= 1000) {
        // fast path (~96% of warps): 4 independent 256-bit loads, front-batched
        ldg256(r0 + c0, a0);
        ldg256(r0 + c1, a1);
        ldg256(r1 + c0, b0);
        ldg256(r1 + c1, b1);
    } else {
        if (id0 < 1000) {
            float s = (float)id0 * 1e-3f;
            sin8(s, c0, a0);
            sin8(s, c1, a1);
        } else {
            ldg256(r0 + c0, a0);
            ldg256(r0 + c1, a1);
        }
        if (id1 < 1000) {
            float s = (float)id1 * 1e-3f;
            sin8(s, c0, b0);
            sin8(s, c1, b1);
        } else {
            ldg256(r1 + c0, b0);
            ldg256(r1 + c1, b1);
        }
    }

    float* o0 = out + (size_t)t0 * DIM;
    float* o1 = o0 + DIM;
    stg256_cs(o0 + c0, a0);
    stg256_cs(o0 + c1, a1);
    stg256_cs(o1 + c0, b0);
    stg256_cs(o1 + c1, b1);
}

extern "C" void kernel_launch(void* const* d_in, const int* in_sizes, int n_in,
                              void* d_out, int out_size)
{
    // metadata order: x (int32), weight (float32), num_value (int32), is_num (bool)
    const int2*  x2 = (const int2*)d_in[0];
    const float* w  = (const float*)d_in[1];
    float*      out = (float*)d_out;

    int n_tokens = in_sizes[0];           // 32768 (even)
    int n_pairs  = n_tokens / 2;          // 16384 warps
    int blocks   = (n_pairs * 32 + 255) / 256;   // 2048

    embed_kernel<<<blocks, 256>>>(x2, w, out, n_pairs);
}

// round 17
// speedup vs baseline: 1.2808x; 1.1233x over previous
#include <cuda_runtime.h>
#include <cuda_bf16.h>

// CustomEmbedding: out[t, :] = sin((id/1000)*(i+1)) if id<1000 else weight[id, :]
// Tokens: 8*4096 = 32768, DIM = 512 floats = 128 float4 per row.
//
// FINAL (measured-best, R6 = 16.10us): the kernel is at the DRAM-write
// roofline (64MB output / 16.1us = 4.0 TB/s ~ HBM3e write-direction cap);
// A/B matrix across MLP depth, persistence, TMA, 256-bit ops, and all store
// policies showed nothing beats this shape.
//
// One WARP per TWO tokens:
//   - both ids fetched with a single int2 LDG (broadcast)
//   - 8 independent row LDG.128s front-batched (per-thread MLP = 8)
//   - 8 streaming STG.128s (__stcs, evict-first): keeps the ~50MB weight
//     working set L2-resident and streams the write-once output to DRAM.
// 256-thread block = 8 warps = 16 tokens; grid = 2048 blocks.

#define DIM4 128            // 512 floats / 4

__device__ __forceinline__ float4 sin4(float s, int jj) {
    float b = (float)(jj * 4);
    float4 v;
    v.x = sinf(s * (b + 1.0f));
    v.y = sinf(s * (b + 2.0f));
    v.z = sinf(s * (b + 3.0f));
    v.w = sinf(s * (b + 4.0f));
    return v;
}

__global__ void __launch_bounds__(256)
embed_kernel(const int2* __restrict__ x2,    // token ids, viewed as pairs
             const float4* __restrict__ w,   // [VOCAB, DIM4]
             float4* __restrict__ out,       // [N, DIM4]
             int n_pairs)
{
    int warp = (blockIdx.x * blockDim.x + threadIdx.x) >> 5;  // global warp = pair idx
    int j    = threadIdx.x & 31;                              // lane -> float4 idx base
    if (warp >= n_pairs) return;

    int2 ids = __ldg(x2 + warp);        // one 8B load, broadcast across warp
    int  id0 = ids.x, id1 = ids.y;
    int  t0  = warp * 2;

    const float4* r0 = w + (size_t)id0 * DIM4;
    const float4* r1 = w + (size_t)id1 * DIM4;

    float4 a0, a1, a2, a3, b0, b1, b2, b3;

    if (id0 >= 1000 && id1 >= 1000) {
        // fast path (~96% of warps): 8 independent loads, front-batched
        a0 = __ldg(r0 + j);
        a1 = __ldg(r0 + j + 32);
        a2 = __ldg(r0 + j + 64);
        a3 = __ldg(r0 + j + 96);
        b0 = __ldg(r1 + j);
        b1 = __ldg(r1 + j + 32);
        b2 = __ldg(r1 + j + 64);
        b3 = __ldg(r1 + j + 96);
    } else {
        if (id0 < 1000) {
            float s = (float)id0 * 1e-3f;
            a0 = sin4(s, j); a1 = sin4(s, j + 32);
            a2 = sin4(s, j + 64); a3 = sin4(s, j + 96);
        } else {
            a0 = __ldg(r0 + j);      a1 = __ldg(r0 + j + 32);
            a2 = __ldg(r0 + j + 64); a3 = __ldg(r0 + j + 96);
        }
        if (id1 < 1000) {
            float s = (float)id1 * 1e-3f;
            b0 = sin4(s, j); b1 = sin4(s, j + 32);
            b2 = sin4(s, j + 64); b3 = sin4(s, j + 96);
        } else {
            b0 = __ldg(r1 + j);      b1 = __ldg(r1 + j + 32);
            b2 = __ldg(r1 + j + 64); b3 = __ldg(r1 + j + 96);
        }
    }

    float4* o0 = out + (size_t)t0 * DIM4;
    float4* o1 = o0 + DIM4;
    __stcs(o0 + j,      a0);
    __stcs(o0 + j + 32, a1);
    __stcs(o0 + j + 64, a2);
    __stcs(o0 + j + 96, a3);
    __stcs(o1 + j,      b0);
    __stcs(o1 + j + 32, b1);
    __stcs(o1 + j + 64, b2);
    __stcs(o1 + j + 96, b3);
}

extern "C" void kernel_launch(void* const* d_in, const int* in_sizes, int n_in,
                              void* d_out, int out_size)
{
    // metadata order: x (int32), weight (float32), num_value (int32), is_num (bool)
    const int2*   x2 = (const int2*)d_in[0];
    const float4* w  = (const float4*)d_in[1];
    float4*      out = (float4*)d_out;

    int n_tokens = in_sizes[0];           // 32768 (even)
    int n_pairs  = n_tokens / 2;          // 16384 warps
    int blocks   = (n_pairs * 32 + 255) / 256;   // 2048

    embed_kernel<<<blocks, 256>>>(x2, w, out, n_pairs);
}